// round 14
// baseline (speedup 1.0000x reference)
#include <cuda_runtime.h>
#include <cuda_bf16.h>

// ---------------- problem constants ----------------
#define SM1n  255
#define NBLK  296          // 2 persistent blocks per SM (148 SMs)
#define REW_OFF  4177920L
#define KL_OFF   4194240L
#define HS_OFF   4194304L
#define SMP_OFF  20905984L
#define ROWSTRIDE_OUT 261120L   // 255*1024

typedef unsigned long long ull;
typedef __nv_bfloat16 bf16;
#define DI __device__ __forceinline__

// ---------------- fp32 scratch ----------------
__device__ float g_ppre  [64L*256*1024];
__device__ float g_logits[64L*255*1024];
__device__ float g_prior [64L*255*1024];
__device__ float g_klbt  [64L*255];
__device__ float g_Gpart [8L*64*4096];
__device__ float g_Lpart [16L*64*1024];
__device__ unsigned g_cnt = 0;
__device__ unsigned g_genA[8*32];   // 8 generation flags, 128B apart

// ---------------- bf16 limb buffers (hi, lo) ----------------
__device__ bf16 bW4h [2048L*4096], bW4l [2048L*4096];
__device__ bf16 bPWth[1024L*1024], bPWtl[1024L*1024];
__device__ bf16 bPWbh[1024L*1024], bPWbl[1024L*1024];
__device__ bf16 bEW1h[256L*1024],  bEW1l[256L*1024];
__device__ bf16 bEW2h[1024L*1024], bEW2l[1024L*1024];
__device__ bf16 bPRh [1024L*1024], bPRl [1024L*1024];
__device__ bf16 bDW1h[2048L*1024], bDW1l[2048L*1024];
__device__ bf16 bDW2h[1024L*256],  bDW2l[1024L*256];
__device__ bf16 bXh  [64L*256*256],  bXl  [64L*256*256];
__device__ bf16 bY1h [64L*256*1024], bY1l [64L*256*1024];
__device__ bf16 bENCh[64L*256*1024], bENCl[64L*256*1024];
__device__ bf16 bHSh [64L*255*1024], bHSl [64L*255*1024];
__device__ bf16 bSMPh[64L*255*1024], bSMPl[64L*255*1024];
__device__ bf16 bDCh [64L*255*1024], bDCl [64L*255*1024];
__device__ bf16 bH0h [64L*1024],     bH0l [64L*1024];

DI float decode_tau(const void* p) {
    unsigned u = *(const unsigned*)p;
    if (u == 0u) return 0.0f;
    if ((u & 0x7f800000u) == 0u) return (float)(int)u;
    return __uint_as_float(u);
}
DI float sigm(float x) { return 1.0f / (1.0f + expf(-x)); }
DI void fsplit(float v, bf16& h, bf16& l) {
    h = __float2bfloat16(v);
    l = __float2bfloat16(v - __bfloat162float(h));
}

// ---------------- mma helpers ----------------
DI unsigned sptr(const void* p){ return (unsigned)__cvta_generic_to_shared(p); }
DI void ldsm4(unsigned r[4], unsigned a){
    asm volatile("ldmatrix.sync.aligned.m8n8.x4.shared.b16 {%0,%1,%2,%3}, [%4];"
        : "=r"(r[0]),"=r"(r[1]),"=r"(r[2]),"=r"(r[3]) : "r"(a));
}
DI void ldsm4t(unsigned r[4], unsigned a){
    asm volatile("ldmatrix.sync.aligned.m8n8.x4.trans.shared.b16 {%0,%1,%2,%3}, [%4];"
        : "=r"(r[0]),"=r"(r[1]),"=r"(r[2]),"=r"(r[3]) : "r"(a));
}
DI void mmab(float c[4], const unsigned a[4], unsigned b0, unsigned b1){
    asm volatile("mma.sync.aligned.m16n8k16.row.col.f32.bf16.bf16.f32 "
        "{%0,%1,%2,%3},{%4,%5,%6,%7},{%8,%9},{%0,%1,%2,%3};"
        : "+f"(c[0]),"+f"(c[1]),"+f"(c[2]),"+f"(c[3])
        : "r"(a[0]),"r"(a[1]),"r"(a[2]),"r"(a[3]),"r"(b0),"r"(b1));
}

struct SmemGemm {
    bf16 A[2][2][64*40];    // [buf][limb][m64 x k32 pad40]
    bf16 B[2][2][32*136];   // [buf][limb][k32 x n128 pad136]
};
#define SMEMSZ ((int)sizeof(SmemGemm))

// ============= core 64x128 GEMM via bf16x3 mma, 256 thr, double-buffered =============
// warp grid: 2 (M) x 4 (N); each warp computes 32 rows x 32 cols.
DI void mma_core(const bf16* __restrict__ A1h, const bf16* __restrict__ A1l, long long lda1,
                 const bf16* __restrict__ A2h, const bf16* __restrict__ A2l, long long lda2, long long K1,
                 const bf16* __restrict__ Wh,  const bf16* __restrict__ Wl,  long long ldw, int K,
                 float* __restrict__ Cf, long long ldc,
                 const float* __restrict__ bias, int relu,
                 bf16* __restrict__ Coh, bf16* __restrict__ Col, long long ldco,
                 SmemGemm* sm)
{
    const int tid  = threadIdx.x;
    const int lane = tid & 31, wid = tid >> 5;
    const int mw = wid >> 2;        // 0..1 : 32-row block
    const int nw = wid & 3;         // 0..3 : 32-col block
    const int arow = tid >> 2, acol = (tid & 3) << 3;
    const int brow = tid >> 3, bcol = (tid & 7) << 4;

    float acc[2][4][4];
#pragma unroll
    for (int i = 0; i < 2; i++)
#pragma unroll
        for (int j = 0; j < 4; j++)
#pragma unroll
            for (int q = 0; q < 4; q++) acc[i][j][q] = 0.0f;

    uint4 vah, valo, vbh0, vbh1, vbl0, vbl1;
    {
        long long k = acol;
        const bf16 *ph, *pl; long long off;
        if (k < K1) { ph = A1h; pl = A1l; off = (long long)arow*lda1 + k; }
        else        { ph = A2h; pl = A2l; off = (long long)arow*lda2 + (k - K1); }
        vah  = *(const uint4*)(ph + off);
        valo = *(const uint4*)(pl + off);
        const bf16* wp = Wh + (long long)brow*ldw + bcol;
        const bf16* wq = Wl + (long long)brow*ldw + bcol;
        vbh0 = *(const uint4*)wp;  vbh1 = *(const uint4*)(wp + 8);
        vbl0 = *(const uint4*)wq;  vbl1 = *(const uint4*)(wq + 8);
    }

    int p = 0;
    for (int k0 = 0; k0 < K; k0 += 32) {
        *(uint4*)&sm->A[p][0][arow*40 + acol] = vah;
        *(uint4*)&sm->A[p][1][arow*40 + acol] = valo;
        *(uint4*)&sm->B[p][0][brow*136 + bcol]     = vbh0;
        *(uint4*)&sm->B[p][0][brow*136 + bcol + 8] = vbh1;
        *(uint4*)&sm->B[p][1][brow*136 + bcol]     = vbl0;
        *(uint4*)&sm->B[p][1][brow*136 + bcol + 8] = vbl1;
        __syncthreads();

        if (k0 + 32 < K) {
            long long k = k0 + 32 + acol;
            const bf16 *ph, *pl; long long off;
            if (k < K1) { ph = A1h; pl = A1l; off = (long long)arow*lda1 + k; }
            else        { ph = A2h; pl = A2l; off = (long long)arow*lda2 + (k - K1); }
            vah  = *(const uint4*)(ph + off);
            valo = *(const uint4*)(pl + off);
            const bf16* wp = Wh + (long long)(k0 + 32 + brow)*ldw + bcol;
            const bf16* wq = Wl + (long long)(k0 + 32 + brow)*ldw + bcol;
            vbh0 = *(const uint4*)wp;  vbh1 = *(const uint4*)(wp + 8);
            vbl0 = *(const uint4*)wq;  vbl1 = *(const uint4*)(wq + 8);
        }

#pragma unroll
        for (int kk = 0; kk < 2; kk++) {
            unsigned ah[2][4], al[2][4];
#pragma unroll
            for (int mt = 0; mt < 2; mt++) {
                int aoff = (mw*32 + mt*16 + (lane & 15))*40 + kk*16 + ((lane >> 4) << 3);
                ldsm4(ah[mt], sptr(&sm->A[p][0][aoff]));
                ldsm4(al[mt], sptr(&sm->A[p][1][aoff]));
            }
            int brow0 = kk*16 + (lane & 7) + (lane & 8);
#pragma unroll
            for (int g = 0; g < 2; g++) {
                int boff = brow0*136 + nw*32 + g*16 + ((lane & 16) >> 1);
                unsigned bh[4], bl[4];
                ldsm4t(bh, sptr(&sm->B[p][0][boff]));
                ldsm4t(bl, sptr(&sm->B[p][1][boff]));
#pragma unroll
                for (int mt = 0; mt < 2; mt++) {
                    mmab(acc[mt][g*2],   ah[mt], bh[0], bh[1]);
                    mmab(acc[mt][g*2],   ah[mt], bl[0], bl[1]);
                    mmab(acc[mt][g*2],   al[mt], bh[0], bh[1]);
                    mmab(acc[mt][g*2+1], ah[mt], bh[2], bh[3]);
                    mmab(acc[mt][g*2+1], ah[mt], bl[2], bl[3]);
                    mmab(acc[mt][g*2+1], al[mt], bh[2], bh[3]);
                }
            }
        }
        p ^= 1;
    }

#pragma unroll
    for (int mt = 0; mt < 2; mt++) {
        const int r0 = mw*32 + mt*16 + (lane >> 2);
#pragma unroll
        for (int n8 = 0; n8 < 4; n8++) {
            int col = nw*32 + n8*8 + (lane & 3)*2;
            float v00 = acc[mt][n8][0], v01 = acc[mt][n8][1];
            float v10 = acc[mt][n8][2], v11 = acc[mt][n8][3];
            if (bias) {
                float b0 = bias[col], b1 = bias[col+1];
                v00 += b0; v01 += b1; v10 += b0; v11 += b1;
            }
            if (relu) {
                v00 = fmaxf(v00, 0.f); v01 = fmaxf(v01, 0.f);
                v10 = fmaxf(v10, 0.f); v11 = fmaxf(v11, 0.f);
            }
            if (Cf) {
                *(float2*)(Cf + (long long)r0*ldc + col)     = make_float2(v00, v01);
                *(float2*)(Cf + (long long)(r0+8)*ldc + col) = make_float2(v10, v11);
            }
            if (Coh) {
                bf16 h0,l0,h1,l1;
                fsplit(v00,h0,l0); fsplit(v01,h1,l1);
                *(__nv_bfloat162*)(Coh + (long long)r0*ldco + col) = __nv_bfloat162(h0,h1);
                *(__nv_bfloat162*)(Col + (long long)r0*ldco + col) = __nv_bfloat162(l0,l1);
                fsplit(v10,h0,l0); fsplit(v11,h1,l1);
                *(__nv_bfloat162*)(Coh + (long long)(r0+8)*ldco + col) = __nv_bfloat162(h0,h1);
                *(__nv_bfloat162*)(Col + (long long)(r0+8)*ldco + col) = __nv_bfloat162(l0,l1);
            }
        }
    }
}

// ---------------- global GEMM wrapper (2 blocks/SM) ----------------
__global__ void __launch_bounds__(256, 2)
mma_sgemm(const bf16* A1h, const bf16* A1l, long long lda1,
          const bf16* A2h, const bf16* A2l, long long lda2, long long K1,
          const bf16* Wh, const bf16* Wl, long long ldw, int K,
          const float* bias, int relu,
          float* Cf, long long ldc,
          bf16* Coh, bf16* Col, long long ldco)
{
    extern __shared__ char dyn[];
    SmemGemm* sm = (SmemGemm*)dyn;
    long long m0 = (long long)blockIdx.y * 64;
    long long n0 = (long long)blockIdx.x * 128;
    mma_core(A1h + m0*lda1, A1l + m0*lda1, lda1,
             A2h + m0*lda2, A2l + m0*lda2, lda2, K1,
             Wh + n0, Wl + n0, ldw, K,
             Cf ? Cf + m0*ldc + n0 : nullptr, ldc,
             bias ? bias + n0 : nullptr, relu,
             Coh ? Coh + m0*ldco + n0 : nullptr,
             Col ? Col + m0*ldco + n0 : nullptr, ldco, sm);
}

// ---------------- GRU combine for one element ----------------
DI float gru_elem(const float* __restrict__ Gpart, const float* __restrict__ on,
                  const float* __restrict__ bi, const float* __restrict__ bh,
                  const float* __restrict__ o_hs, int b, int j, int t)
{
    long bb = (long)b * 4096;
    float sr  = on[j]        + bi[j]        + bh[j];
    float sz  = on[1024+j]   + bi[1024+j]   + bh[1024+j];
    float inn = on[2048+j]   + bi[2048+j];
    float hn  = bh[2048+j];
#pragma unroll
    for (int ks = 0; ks < 8; ks++) {
        const float* G = Gpart + (long)ks * 262144 + bb;
        sr  += G[j];
        sz  += G[1024 + j];
        inn += G[2048 + j];
        hn  += G[3072 + j];
    }
    float r = sigm(sr), z = sigm(sz);
    float nn = tanhf(inn + r * hn);
    float hp = (t == 0) ? 0.0f : o_hs[((long)b * 255 + t - 1) * 1024 + j];
    return (1.0f - z) * nn + z * hp;
}

// ---------------- k_init: h0 limbs ----------------
__global__ void k_init(bf16* __restrict__ h, bf16* __restrict__ l)
{
    int i = blockIdx.x * 256 + threadIdx.x;
    if (i < 65536) { h[i] = __float2bfloat16(0.f); l[i] = __float2bfloat16(0.f); }
}

// ---------------- k_prep: ALL weight conversions ----------------
#define PREP_TOTAL 15204352L
__global__ void k_prep(const float* __restrict__ wi, const float* __restrict__ wh,
                       const float* __restrict__ enc_w1, const float* __restrict__ enc_w2,
                       const float* __restrict__ post_w, const float* __restrict__ prior_w,
                       const float* __restrict__ dec_w1, const float* __restrict__ dec_w2)
{
    long i = (long)blockIdx.x * 256 + threadIdx.x;
    if (i < 8388608L) {
        int n = (int)(i & 4095);
        int k = (int)(i >> 12);
        float v;
        if (k < 1024) {
            v = (n < 3072) ? wi[(long)k * 3072 + n] : 0.0f;
        } else {
            int k2 = k - 1024;
            if      (n < 2048) v = wh[(long)k2 * 3072 + n];
            else if (n < 3072) v = 0.0f;
            else               v = wh[(long)k2 * 3072 + 2048 + (n - 3072)];
        }
        fsplit(v, bW4h[i], bW4l[i]);
        return;
    }
    long j = i - 8388608L;
    if (j < 262144L)  { fsplit(enc_w1[j], bEW1h[j], bEW1l[j]); return; }
    j -= 262144L;
    if (j < 1048576L) { fsplit(enc_w2[j], bEW2h[j], bEW2l[j]); return; }
    j -= 1048576L;
    if (j < 1048576L) { fsplit(post_w[j], bPWth[j], bPWtl[j]); return; }
    j -= 1048576L;
    if (j < 1048576L) { fsplit(post_w[1048576L + j], bPWbh[j], bPWbl[j]); return; }
    j -= 1048576L;
    if (j < 1048576L) { fsplit(prior_w[j], bPRh[j], bPRl[j]); return; }
    j -= 1048576L;
    if (j < 2097152L) { fsplit(dec_w1[j], bDW1h[j], bDW1l[j]); return; }
    j -= 2097152L;
    fsplit(dec_w2[j], bDW2h[j], bDW2l[j]);
}

// ---------------- LayerNorm -> bf16 limbs ----------------
__global__ void k_ln(const float* __restrict__ obs, const float* __restrict__ g,
                     const float* __restrict__ bvec, bf16* __restrict__ oh, bf16* __restrict__ ol)
{
    int row = blockIdx.x, c = threadIdx.x;
    __shared__ float red[256];
    float x = obs[(long)row * 256 + c];
    red[c] = x; __syncthreads();
    for (int s = 128; s > 0; s >>= 1) { if (c < s) red[c] += red[c + s]; __syncthreads(); }
    float mu = red[0] * (1.0f / 256.0f);
    __syncthreads();
    float d = x - mu;
    red[c] = d * d; __syncthreads();
    for (int s = 128; s > 0; s >>= 1) { if (c < s) red[c] += red[c + s]; __syncthreads(); }
    float var = red[0] * (1.0f / 256.0f);
    float v = d * rsqrtf(var + 1e-5f) * g[c] + bvec[c];
    fsplit(v, oh[(long)row * 256 + c], ol[(long)row * 256 + c]);
}

// ---------------- grid barrier: sharded gen flags, release/acquire ----------------
DI unsigned atom_add_acqrel(unsigned* p, unsigned v){
    unsigned old;
    asm volatile("atom.add.acq_rel.gpu.u32 %0, [%1], %2;" : "=r"(old) : "l"(p), "r"(v) : "memory");
    return old;
}
DI unsigned ld_acq(unsigned* p){
    unsigned v;
    asm volatile("ld.acquire.gpu.u32 %0, [%1];" : "=r"(v) : "l"(p) : "memory");
    return v;
}
DI void st_rel(unsigned* p, unsigned v){
    asm volatile("st.release.gpu.u32 [%0], %1;" :: "l"(p), "r"(v) : "memory");
}
DI void st_relaxed(unsigned* p, unsigned v){
    asm volatile("st.relaxed.gpu.u32 [%0], %1;" :: "l"(p), "r"(v) : "memory");
}
DI void gsync(unsigned &gen) {
    __syncthreads();
    if (threadIdx.x == 0) {
        if (atom_add_acqrel(&g_cnt, 1u) == NBLK - 1u) {
            st_relaxed(&g_cnt, 0u);
#pragma unroll
            for (int i = 0; i < 8; i++) st_rel(&g_genA[i * 32], gen + 1u);
        }
        unsigned* myflag = &g_genA[(blockIdx.x & 7) * 32];
        while (ld_acq(myflag) == gen) { }
    }
    __syncthreads();
    gen++;
}

// ---------------- persistent scan: ppre GEMM + s0 softmax + 255 steps ----------------
__global__ void __launch_bounds__(256, 2)
k_scan(float* __restrict__ o_smp, float* __restrict__ o_hs, float* __restrict__ lg,
       float* __restrict__ ppre, const float* __restrict__ gum,
       const int*   __restrict__ act,
       const float* __restrict__ wi, const float* __restrict__ bi,
       const float* __restrict__ bh, const float* __restrict__ post_b,
       const void*  __restrict__ tau_ptr,
       float* __restrict__ Gpart, float* __restrict__ Lpart)
{
    extern __shared__ char dyn[];
    SmemGemm* sm = (SmemGemm*)dyn;
    unsigned gen = ld_acq(&g_genA[(blockIdx.x & 7) * 32]);
    const float tau = decode_tau(tau_ptr);
    const int tid  = threadIdx.x;
    const int gtid = blockIdx.x * 256 + tid;
    const int warp = blockIdx.x * 8 + (tid >> 5);
    const int lane = tid & 31;

    // ---- pre-phase P0: ppre = enc @ post_w_bot + post_b (2048 tasks)
    for (int task = blockIdx.x; task < 2048; task += NBLK) {
        int mt = task >> 3, nt = task & 7;
        const bf16* Ah = bENCh + (long)mt * 64 * 1024;
        const bf16* Al = bENCl + (long)mt * 64 * 1024;
        mma_core(Ah, Al, 1024, Ah, Al, 1024, 1LL<<40,
                 bPWbh + nt*128, bPWbl + nt*128, 1024, 1024,
                 ppre + (long)mt * 64 * 1024 + nt*128, 1024,
                 post_b + nt*128, 0, nullptr, nullptr, 0, sm);
        __syncthreads();
    }
    gsync(gen);

    // ---- pre-phase P0b: s0 = gumbel_softmax(ppre[:,0] + gum[0])
    for (int g = warp; g < 2048; g += NBLK * 8) {
        int b = g >> 5, l = g & 31;
        int n = l * 32 + lane;
        float x = (ppre[(long)b * 262144 + n] + gum[((long)b * 32 + l) * 32 + lane]) / tau;
        float m = x;
#pragma unroll
        for (int o = 16; o; o >>= 1) m = fmaxf(m, __shfl_xor_sync(0xffffffffu, m, o));
        float e = expf(x - m);
        float s = e;
#pragma unroll
        for (int o = 16; o; o >>= 1) s += __shfl_xor_sync(0xffffffffu, s, o);
        float pv = e / s;
        long oidx = (long)b * ROWSTRIDE_OUT + n;
        o_smp[oidx] = pv;
        fsplit(pv, bSMPh[oidx], bSMPl[oidx]);
    }
    gsync(gen);

    // ---- main loop ----
    for (int t = 0; t < SM1n; t++) {
        // phase 1: gates partials ; 256 tasks = 8 Ksplit x 32 Ntiles
        if (blockIdx.x < 256) {
            int ks = blockIdx.x >> 5;
            int nt = blockIdx.x & 31;
            const bf16 *Ah, *Al; long long lda;
            if (ks < 4) {
                Ah = bSMPh + (long)t*1024 + ks*256;
                Al = bSMPl + (long)t*1024 + ks*256;
                lda = ROWSTRIDE_OUT;
            } else if (t == 0) {
                Ah = bH0h + (ks-4)*256; Al = bH0l + (ks-4)*256; lda = 1024;
            } else {
                Ah = bHSh + (long)(t-1)*1024 + (ks-4)*256;
                Al = bHSl + (long)(t-1)*1024 + (ks-4)*256;
                lda = ROWSTRIDE_OUT;
            }
            mma_core(Ah, Al, lda, Ah, Al, lda, 1LL<<40,
                     bW4h + (long)(ks*256)*4096 + nt*128,
                     bW4l + (long)(ks*256)*4096 + nt*128, 4096, 256,
                     Gpart + (long)ks*262144 + nt*128, 4096,
                     nullptr, 0, nullptr, nullptr, 0, sm);
        }
        gsync(gen);

        // phase 2: GRU combine -> h_new
        for (int idx = gtid; idx < 65536; idx += NBLK * 256) {
            int b = idx >> 10, j = idx & 1023;
            int a = act[b * 256 + t];
            const float* on = wi + (long)(1024 + a) * 3072;
            float hnew = gru_elem(Gpart, on, bi, bh, o_hs, b, j, t);
            long oidx = ((long)b * 255 + t) * 1024 + j;
            o_hs[oidx] = hnew;
            fsplit(hnew, bHSh[oidx], bHSl[oidx]);
        }
        gsync(gen);

        // phase 3: logits partials ; 128 tasks = 16 Ksplit x 8 Ntiles (K=64)
        if (blockIdx.x < 128) {
            int ks = blockIdx.x >> 3;
            int nt = blockIdx.x & 7;
            const bf16* Ah = bHSh + (long)t*1024 + ks*64;
            const bf16* Al = bHSl + (long)t*1024 + ks*64;
            mma_core(Ah, Al, ROWSTRIDE_OUT, Ah, Al, ROWSTRIDE_OUT, 1LL<<40,
                     bPWth + (long)(ks*64)*1024 + nt*128,
                     bPWtl + (long)(ks*64)*1024 + nt*128, 1024, 64,
                     Lpart + (long)ks*65536 + nt*128, 1024,
                     nullptr, 0, nullptr, nullptr, 0, sm);
        }
        gsync(gen);

        // phase 4: sum Lpart + ppre, write lg, gumbel softmax -> s_{t+1}
        for (int g = warp; g < 2048; g += NBLK * 8) {
            int b = g >> 5, l = g & 31;
            int n = l * 32 + lane;
            float acc = 0.0f;
#pragma unroll
            for (int ks = 0; ks < 16; ks++) acc += Lpart[(long)ks * 65536 + b * 1024 + n];
            float logit = acc + ppre[((long)b * 256 + t + 1) * 1024 + n];
            lg[((long)b * 255 + t) * 1024 + n] = logit;
            if (t < SM1n - 1) {
                float x = (logit + gum[(long)(t + 1) * 65536 + ((long)b * 32 + l) * 32 + lane]) / tau;
                float m = x;
#pragma unroll
                for (int o = 16; o; o >>= 1) m = fmaxf(m, __shfl_xor_sync(0xffffffffu, m, o));
                float e = expf(x - m);
                float s = e;
#pragma unroll
                for (int o = 16; o; o >>= 1) s += __shfl_xor_sync(0xffffffffu, s, o);
                float pv = e / s;
                long oidx = ((long)b * 255 + (t + 1)) * 1024 + n;
                o_smp[oidx] = pv;
                fsplit(pv, bSMPh[oidx], bSMPl[oidx]);
            }
        }
        gsync(gen);
    }
}

// ---------------- KL ----------------
__global__ void k_kl(const float* __restrict__ post, const float* __restrict__ prior,
                     float* __restrict__ klbt)
{
    int row = blockIdx.x;
    int wid = threadIdx.x >> 5, lane = threadIdx.x & 31;
    float acc = 0.0f;
    for (int l = wid; l < 32; l += 8) {
        long base = (long)row * 1024 + l * 32 + lane;
        float xp = post[base], xq = prior[base];
        float mp = xp, mq = xq;
#pragma unroll
        for (int o = 16; o; o >>= 1) {
            mp = fmaxf(mp, __shfl_xor_sync(0xffffffffu, mp, o));
            mq = fmaxf(mq, __shfl_xor_sync(0xffffffffu, mq, o));
        }
        float ep = expf(xp - mp), eq = expf(xq - mq);
        float sp = ep, sq = eq;
#pragma unroll
        for (int o = 16; o; o >>= 1) {
            sp += __shfl_xor_sync(0xffffffffu, sp, o);
            sq += __shfl_xor_sync(0xffffffffu, sq, o);
        }
        float lpp = xp - mp - logf(sp);
        float lpq = xq - mq - logf(sq);
        float pp = expf(lpp), pq = expf(lpq);
        acc += 0.8f * pp * (lpp - lpq) + 0.2f * pq * (lpq - lpp);
    }
    __shared__ float red[256];
    red[threadIdx.x] = acc; __syncthreads();
    for (int s = 128; s > 0; s >>= 1) { if (threadIdx.x < s) red[threadIdx.x] += red[threadIdx.x + s]; __syncthreads(); }
    if (threadIdx.x == 0) klbt[row] = fmaxf(red[0] - 1.0f, 0.0f);
}

__global__ void k_klreduce(const float* __restrict__ klbt, float* __restrict__ out)
{
    int b = blockIdx.x, t = threadIdx.x;
    __shared__ float red[256];
    red[t] = (t < 255) ? klbt[b * 255 + t] : 0.0f;
    __syncthreads();
    for (int s = 128; s > 0; s >>= 1) { if (t < s) red[t] += red[t + s]; __syncthreads(); }
    if (t == 0) out[b] = red[0] * (1.0f / 255.0f);
}

__global__ void k_reward(const float* __restrict__ hs, const float* __restrict__ smp,
                         const float* __restrict__ rw, const float* __restrict__ rb,
                         float* __restrict__ out)
{
    int row = blockIdx.x * 8 + (threadIdx.x >> 5);
    int lane = threadIdx.x & 31;
    if (row >= 64 * 255) return;
    float acc = 0.0f;
    for (int k = lane; k < 1024; k += 32) acc += hs[(long)row * 1024 + k] * rw[k];
    for (int k = lane; k < 1024; k += 32) acc += smp[(long)row * 1024 + k] * rw[1024 + k];
#pragma unroll
    for (int o = 16; o; o >>= 1) acc += __shfl_xor_sync(0xffffffffu, acc, o);
    if (lane == 0) out[row] = acc + rb[0];
}

// ---------------- host ----------------
extern "C" void kernel_launch(void* const* d_in, const int* in_sizes, int n_in,
                              void* d_out, int out_size)
{
    const float* obs    = (const float*)d_in[0];
    const int*   act    = (const int*)  d_in[1];
    const float* gum    = (const float*)d_in[2];
    const void*  tau    =               d_in[3];
    const float* ln_g   = (const float*)d_in[4];
    const float* ln_b   = (const float*)d_in[5];
    const float* enc_w1 = (const float*)d_in[6];
    const float* enc_b1 = (const float*)d_in[7];
    const float* enc_w2 = (const float*)d_in[8];
    const float* enc_b2 = (const float*)d_in[9];
    const float* gru_wi = (const float*)d_in[10];
    const float* gru_wh = (const float*)d_in[11];
    const float* gru_bi = (const float*)d_in[12];
    const float* gru_bh = (const float*)d_in[13];
    const float* prior_w= (const float*)d_in[14];
    const float* prior_b= (const float*)d_in[15];
    const float* post_w = (const float*)d_in[16];
    const float* post_b = (const float*)d_in[17];
    const float* dec_w1 = (const float*)d_in[18];
    const float* dec_b1 = (const float*)d_in[19];
    const float* dec_w2 = (const float*)d_in[20];
    const float* dec_b2 = (const float*)d_in[21];
    const float* rew_w  = (const float*)d_in[22];
    const float* rew_b  = (const float*)d_in[23];

    float* out     = (float*)d_out;
    float* o_recon = out;
    float* o_rew   = out + REW_OFF;
    float* o_kl    = out + KL_OFF;
    float* o_hs    = out + HS_OFF;
    float* o_smp   = out + SMP_OFF;

    cudaFuncSetAttribute(mma_sgemm, cudaFuncAttributeMaxDynamicSharedMemorySize, SMEMSZ);
    cudaFuncSetAttribute(k_scan,    cudaFuncAttributeMaxDynamicSharedMemorySize, SMEMSZ);

#define SYM(T, var, sym) T* var; cudaGetSymbolAddress((void**)&var, sym)
    SYM(float, ppre, g_ppre);  SYM(float, lg, g_logits);  SYM(float, pri, g_prior);
    SYM(float, klbt, g_klbt);  SYM(float, Gp, g_Gpart);   SYM(float, Lp, g_Lpart);
    SYM(bf16, prh, bPRh);   SYM(bf16, prl, bPRl);
    SYM(bf16, dw1h, bDW1h); SYM(bf16, dw1l, bDW1l);
    SYM(bf16, dw2h, bDW2h); SYM(bf16, dw2l, bDW2l);
    SYM(bf16, ew1h, bEW1h); SYM(bf16, ew1l, bEW1l);
    SYM(bf16, ew2h, bEW2h); SYM(bf16, ew2l, bEW2l);
    SYM(bf16, xh, bXh);     SYM(bf16, xl, bXl);
    SYM(bf16, y1h, bY1h);   SYM(bf16, y1l, bY1l);
    SYM(bf16, ench, bENCh); SYM(bf16, encl, bENCl);
    SYM(bf16, hsh, bHSh);   SYM(bf16, hsl, bHSl);
    SYM(bf16, smph, bSMPh); SYM(bf16, smpl, bSMPl);
    SYM(bf16, dch, bDCh);   SYM(bf16, dcl, bDCl);
    SYM(bf16, h0h, bH0h);   SYM(bf16, h0l, bH0l);
#undef SYM

    k_init<<<256, 256>>>(h0h, h0l);
    k_prep<<<(int)(PREP_TOTAL / 256), 256>>>(gru_wi, gru_wh, enc_w1, enc_w2,
                                             post_w, prior_w, dec_w1, dec_w2);
    k_ln<<<16384, 256>>>(obs, ln_g, ln_b, xh, xl);
    mma_sgemm<<<dim3(8,256), 256, SMEMSZ>>>(xh, xl, 256, xh, xl, 256, 1LL<<40,
        ew1h, ew1l, 1024, 256, enc_b1, 1, nullptr, 0, y1h, y1l, 1024);
    mma_sgemm<<<dim3(8,256), 256, SMEMSZ>>>(y1h, y1l, 1024, y1h, y1l, 1024, 1LL<<40,
        ew2h, ew2l, 1024, 1024, enc_b2, 1, nullptr, 0, ench, encl, 1024);

    // persistent scan
    k_scan<<<NBLK, 256, SMEMSZ>>>(o_smp, o_hs, lg, ppre, gum, act,
                                  gru_wi, gru_bi, gru_bh, post_b, tau, Gp, Lp);

    // epilogue heads
    mma_sgemm<<<dim3(8,255), 256, SMEMSZ>>>(hsh, hsl, 1024, hsh, hsl, 1024, 1LL<<40,
        prh, prl, 1024, 1024, prior_b, 0, pri, 1024, nullptr, nullptr, 0);
    k_kl<<<64 * 255, 256>>>(lg, pri, klbt);
    k_klreduce<<<64, 256>>>(klbt, o_kl);
    mma_sgemm<<<dim3(8,255), 256, SMEMSZ>>>(hsh, hsl, 1024, smph, smpl, 1024, 1024,
        dw1h, dw1l, 1024, 2048, dec_b1, 1, nullptr, 0, dch, dcl, 1024);
    mma_sgemm<<<dim3(2,255), 256, SMEMSZ>>>(dch, dcl, 1024, dch, dcl, 1024, 1LL<<40,
        dw2h, dw2l, 256, 1024, dec_b2, 0, o_recon, 256, nullptr, nullptr, 0);
    k_reward<<<2040, 256>>>(o_hs, o_smp, rew_w, rew_b, o_rew);

    (void)in_sizes; (void)n_in; (void)out_size;
}

// round 15
// speedup vs baseline: 1.1967x; 1.1967x over previous
#include <cuda_runtime.h>
#include <cuda_bf16.h>

// ---------------- problem constants ----------------
#define SM1n  255
#define NBLK  296          // 2 persistent blocks per SM (148 SMs)
#define REW_OFF  4177920L
#define KL_OFF   4194240L
#define HS_OFF   4194304L
#define SMP_OFF  20905984L
#define ROWSTRIDE_OUT 261120L   // 255*1024

typedef unsigned long long ull;
typedef __nv_bfloat16 bf16;
#define DI __device__ __forceinline__

// ---------------- fp32 scratch ----------------
__device__ float g_ppre  [64L*256*1024];
__device__ float g_logits[64L*255*1024];
__device__ float g_prior [64L*255*1024];
__device__ float g_klbt  [64L*255];
__device__ float g_Gpart [8L*64*4096];
__device__ float g_Lpart [16L*64*1024];
__device__ unsigned g_cnt = 0;
__device__ unsigned g_gen = 0;

// ---------------- bf16 limb buffers (hi, lo) ----------------
__device__ bf16 bW4h [2048L*4096], bW4l [2048L*4096];
__device__ bf16 bPWth[1024L*1024], bPWtl[1024L*1024];
__device__ bf16 bPWbh[1024L*1024], bPWbl[1024L*1024];
__device__ bf16 bEW1h[256L*1024],  bEW1l[256L*1024];
__device__ bf16 bEW2h[1024L*1024], bEW2l[1024L*1024];
__device__ bf16 bPRh [1024L*1024], bPRl [1024L*1024];
__device__ bf16 bDW1h[2048L*1024], bDW1l[2048L*1024];
__device__ bf16 bDW2h[1024L*256],  bDW2l[1024L*256];
__device__ bf16 bXh  [64L*256*256],  bXl  [64L*256*256];
__device__ bf16 bY1h [64L*256*1024], bY1l [64L*256*1024];
__device__ bf16 bENCh[64L*256*1024], bENCl[64L*256*1024];
__device__ bf16 bHSh [64L*255*1024], bHSl [64L*255*1024];
__device__ bf16 bSMPh[64L*255*1024], bSMPl[64L*255*1024];
__device__ bf16 bDCh [64L*255*1024], bDCl [64L*255*1024];
__device__ bf16 bH0h [64L*1024],     bH0l [64L*1024];

DI float decode_tau(const void* p) {
    unsigned u = *(const unsigned*)p;
    if (u == 0u) return 0.0f;
    if ((u & 0x7f800000u) == 0u) return (float)(int)u;
    return __uint_as_float(u);
}
DI float sigm(float x) { return 1.0f / (1.0f + expf(-x)); }
DI void fsplit(float v, bf16& h, bf16& l) {
    h = __float2bfloat16(v);
    l = __float2bfloat16(v - __bfloat162float(h));
}

// ---------------- mma helpers ----------------
DI unsigned sptr(const void* p){ return (unsigned)__cvta_generic_to_shared(p); }
DI void ldsm4(unsigned r[4], unsigned a){
    asm volatile("ldmatrix.sync.aligned.m8n8.x4.shared.b16 {%0,%1,%2,%3}, [%4];"
        : "=r"(r[0]),"=r"(r[1]),"=r"(r[2]),"=r"(r[3]) : "r"(a));
}
DI void ldsm4t(unsigned r[4], unsigned a){
    asm volatile("ldmatrix.sync.aligned.m8n8.x4.trans.shared.b16 {%0,%1,%2,%3}, [%4];"
        : "=r"(r[0]),"=r"(r[1]),"=r"(r[2]),"=r"(r[3]) : "r"(a));
}
DI void mmab(float c[4], const unsigned a[4], unsigned b0, unsigned b1){
    asm volatile("mma.sync.aligned.m16n8k16.row.col.f32.bf16.bf16.f32 "
        "{%0,%1,%2,%3},{%4,%5,%6,%7},{%8,%9},{%0,%1,%2,%3};"
        : "+f"(c[0]),"+f"(c[1]),"+f"(c[2]),"+f"(c[3])
        : "r"(a[0]),"r"(a[1]),"r"(a[2]),"r"(a[3]),"r"(b0),"r"(b1));
}

struct SmemGemm {
    bf16 A[2][2][64*40];    // [buf][limb][m64 x k32 pad40]
    bf16 B[2][2][32*136];   // [buf][limb][k32 x n128 pad136]
};
#define SMEMSZ ((int)sizeof(SmemGemm))

// ============= core 64x128 GEMM via bf16x3 mma, 256 thr, double-buffered =============
// warp grid: 2 (M) x 4 (N); each warp computes 32 rows x 32 cols.
DI void mma_core(const bf16* __restrict__ A1h, const bf16* __restrict__ A1l, long long lda1,
                 const bf16* __restrict__ A2h, const bf16* __restrict__ A2l, long long lda2, long long K1,
                 const bf16* __restrict__ Wh,  const bf16* __restrict__ Wl,  long long ldw, int K,
                 float* __restrict__ Cf, long long ldc,
                 const float* __restrict__ bias, int relu,
                 bf16* __restrict__ Coh, bf16* __restrict__ Col, long long ldco,
                 SmemGemm* sm)
{
    const int tid  = threadIdx.x;
    const int lane = tid & 31, wid = tid >> 5;
    const int mw = wid >> 2;
    const int nw = wid & 3;
    const int arow = tid >> 2, acol = (tid & 3) << 3;
    const int brow = tid >> 3, bcol = (tid & 7) << 4;

    float acc[2][4][4];
#pragma unroll
    for (int i = 0; i < 2; i++)
#pragma unroll
        for (int j = 0; j < 4; j++)
#pragma unroll
            for (int q = 0; q < 4; q++) acc[i][j][q] = 0.0f;

    uint4 vah, valo, vbh0, vbh1, vbl0, vbl1;
    {
        long long k = acol;
        const bf16 *ph, *pl; long long off;
        if (k < K1) { ph = A1h; pl = A1l; off = (long long)arow*lda1 + k; }
        else        { ph = A2h; pl = A2l; off = (long long)arow*lda2 + (k - K1); }
        vah  = *(const uint4*)(ph + off);
        valo = *(const uint4*)(pl + off);
        const bf16* wp = Wh + (long long)brow*ldw + bcol;
        const bf16* wq = Wl + (long long)brow*ldw + bcol;
        vbh0 = *(const uint4*)wp;  vbh1 = *(const uint4*)(wp + 8);
        vbl0 = *(const uint4*)wq;  vbl1 = *(const uint4*)(wq + 8);
    }

    int p = 0;
    for (int k0 = 0; k0 < K; k0 += 32) {
        *(uint4*)&sm->A[p][0][arow*40 + acol] = vah;
        *(uint4*)&sm->A[p][1][arow*40 + acol] = valo;
        *(uint4*)&sm->B[p][0][brow*136 + bcol]     = vbh0;
        *(uint4*)&sm->B[p][0][brow*136 + bcol + 8] = vbh1;
        *(uint4*)&sm->B[p][1][brow*136 + bcol]     = vbl0;
        *(uint4*)&sm->B[p][1][brow*136 + bcol + 8] = vbl1;
        __syncthreads();

        if (k0 + 32 < K) {
            long long k = k0 + 32 + acol;
            const bf16 *ph, *pl; long long off;
            if (k < K1) { ph = A1h; pl = A1l; off = (long long)arow*lda1 + k; }
            else        { ph = A2h; pl = A2l; off = (long long)arow*lda2 + (k - K1); }
            vah  = *(const uint4*)(ph + off);
            valo = *(const uint4*)(pl + off);
            const bf16* wp = Wh + (long long)(k0 + 32 + brow)*ldw + bcol;
            const bf16* wq = Wl + (long long)(k0 + 32 + brow)*ldw + bcol;
            vbh0 = *(const uint4*)wp;  vbh1 = *(const uint4*)(wp + 8);
            vbl0 = *(const uint4*)wq;  vbl1 = *(const uint4*)(wq + 8);
        }

#pragma unroll
        for (int kk = 0; kk < 2; kk++) {
            unsigned ah[2][4], al[2][4];
#pragma unroll
            for (int mt = 0; mt < 2; mt++) {
                int aoff = (mw*32 + mt*16 + (lane & 15))*40 + kk*16 + ((lane >> 4) << 3);
                ldsm4(ah[mt], sptr(&sm->A[p][0][aoff]));
                ldsm4(al[mt], sptr(&sm->A[p][1][aoff]));
            }
            int brow0 = kk*16 + (lane & 7) + (lane & 8);
#pragma unroll
            for (int g = 0; g < 2; g++) {
                int boff = brow0*136 + nw*32 + g*16 + ((lane & 16) >> 1);
                unsigned bh[4], bl[4];
                ldsm4t(bh, sptr(&sm->B[p][0][boff]));
                ldsm4t(bl, sptr(&sm->B[p][1][boff]));
#pragma unroll
                for (int mt = 0; mt < 2; mt++) {
                    mmab(acc[mt][g*2],   ah[mt], bh[0], bh[1]);
                    mmab(acc[mt][g*2],   ah[mt], bl[0], bl[1]);
                    mmab(acc[mt][g*2],   al[mt], bh[0], bh[1]);
                    mmab(acc[mt][g*2+1], ah[mt], bh[2], bh[3]);
                    mmab(acc[mt][g*2+1], ah[mt], bl[2], bl[3]);
                    mmab(acc[mt][g*2+1], al[mt], bh[2], bh[3]);
                }
            }
        }
        p ^= 1;
    }

#pragma unroll
    for (int mt = 0; mt < 2; mt++) {
        const int r0 = mw*32 + mt*16 + (lane >> 2);
#pragma unroll
        for (int n8 = 0; n8 < 4; n8++) {
            int col = nw*32 + n8*8 + (lane & 3)*2;
            float v00 = acc[mt][n8][0], v01 = acc[mt][n8][1];
            float v10 = acc[mt][n8][2], v11 = acc[mt][n8][3];
            if (bias) {
                float b0 = bias[col], b1 = bias[col+1];
                v00 += b0; v01 += b1; v10 += b0; v11 += b1;
            }
            if (relu) {
                v00 = fmaxf(v00, 0.f); v01 = fmaxf(v01, 0.f);
                v10 = fmaxf(v10, 0.f); v11 = fmaxf(v11, 0.f);
            }
            if (Cf) {
                *(float2*)(Cf + (long long)r0*ldc + col)     = make_float2(v00, v01);
                *(float2*)(Cf + (long long)(r0+8)*ldc + col) = make_float2(v10, v11);
            }
            if (Coh) {
                bf16 h0,l0,h1,l1;
                fsplit(v00,h0,l0); fsplit(v01,h1,l1);
                *(__nv_bfloat162*)(Coh + (long long)r0*ldco + col) = __nv_bfloat162(h0,h1);
                *(__nv_bfloat162*)(Col + (long long)r0*ldco + col) = __nv_bfloat162(l0,l1);
                fsplit(v10,h0,l0); fsplit(v11,h1,l1);
                *(__nv_bfloat162*)(Coh + (long long)(r0+8)*ldco + col) = __nv_bfloat162(h0,h1);
                *(__nv_bfloat162*)(Col + (long long)(r0+8)*ldco + col) = __nv_bfloat162(l0,l1);
            }
        }
    }
}

// ---------------- global GEMM wrapper (2 blocks/SM) ----------------
__global__ void __launch_bounds__(256, 2)
mma_sgemm(const bf16* A1h, const bf16* A1l, long long lda1,
          const bf16* A2h, const bf16* A2l, long long lda2, long long K1,
          const bf16* Wh, const bf16* Wl, long long ldw, int K,
          const float* bias, int relu,
          float* Cf, long long ldc,
          bf16* Coh, bf16* Col, long long ldco)
{
    extern __shared__ char dyn[];
    SmemGemm* sm = (SmemGemm*)dyn;
    long long m0 = (long long)blockIdx.y * 64;
    long long n0 = (long long)blockIdx.x * 128;
    mma_core(A1h + m0*lda1, A1l + m0*lda1, lda1,
             A2h + m0*lda2, A2l + m0*lda2, lda2, K1,
             Wh + n0, Wl + n0, ldw, K,
             Cf ? Cf + m0*ldc + n0 : nullptr, ldc,
             bias ? bias + n0 : nullptr, relu,
             Coh ? Coh + m0*ldco + n0 : nullptr,
             Col ? Col + m0*ldco + n0 : nullptr, ldco, sm);
}

// ---------------- k_init: h0 limbs ----------------
__global__ void k_init(bf16* __restrict__ h, bf16* __restrict__ l)
{
    int i = blockIdx.x * 256 + threadIdx.x;
    if (i < 65536) { h[i] = __float2bfloat16(0.f); l[i] = __float2bfloat16(0.f); }
}

// ---------------- k_prep: ALL weight conversions ----------------
#define PREP_TOTAL 15204352L
__global__ void k_prep(const float* __restrict__ wi, const float* __restrict__ wh,
                       const float* __restrict__ enc_w1, const float* __restrict__ enc_w2,
                       const float* __restrict__ post_w, const float* __restrict__ prior_w,
                       const float* __restrict__ dec_w1, const float* __restrict__ dec_w2)
{
    long i = (long)blockIdx.x * 256 + threadIdx.x;
    if (i < 8388608L) {
        int n = (int)(i & 4095);
        int k = (int)(i >> 12);
        float v;
        if (k < 1024) {
            v = (n < 3072) ? wi[(long)k * 3072 + n] : 0.0f;
        } else {
            int k2 = k - 1024;
            if      (n < 2048) v = wh[(long)k2 * 3072 + n];
            else if (n < 3072) v = 0.0f;
            else               v = wh[(long)k2 * 3072 + 2048 + (n - 3072)];
        }
        fsplit(v, bW4h[i], bW4l[i]);
        return;
    }
    long j = i - 8388608L;
    if (j < 262144L)  { fsplit(enc_w1[j], bEW1h[j], bEW1l[j]); return; }
    j -= 262144L;
    if (j < 1048576L) { fsplit(enc_w2[j], bEW2h[j], bEW2l[j]); return; }
    j -= 1048576L;
    if (j < 1048576L) { fsplit(post_w[j], bPWth[j], bPWtl[j]); return; }
    j -= 1048576L;
    if (j < 1048576L) { fsplit(post_w[1048576L + j], bPWbh[j], bPWbl[j]); return; }
    j -= 1048576L;
    if (j < 1048576L) { fsplit(prior_w[j], bPRh[j], bPRl[j]); return; }
    j -= 1048576L;
    if (j < 2097152L) { fsplit(dec_w1[j], bDW1h[j], bDW1l[j]); return; }
    j -= 2097152L;
    fsplit(dec_w2[j], bDW2h[j], bDW2l[j]);
}

// ---------------- LayerNorm -> bf16 limbs ----------------
__global__ void k_ln(const float* __restrict__ obs, const float* __restrict__ g,
                     const float* __restrict__ bvec, bf16* __restrict__ oh, bf16* __restrict__ ol)
{
    int row = blockIdx.x, c = threadIdx.x;
    __shared__ float red[256];
    float x = obs[(long)row * 256 + c];
    red[c] = x; __syncthreads();
    for (int s = 128; s > 0; s >>= 1) { if (c < s) red[c] += red[c + s]; __syncthreads(); }
    float mu = red[0] * (1.0f / 256.0f);
    __syncthreads();
    float d = x - mu;
    red[c] = d * d; __syncthreads();
    for (int s = 128; s > 0; s >>= 1) { if (c < s) red[c] += red[c + s]; __syncthreads(); }
    float var = red[0] * (1.0f / 256.0f);
    float v = d * rsqrtf(var + 1e-5f) * g[c] + bvec[c];
    fsplit(v, oh[(long)row * 256 + c], ol[(long)row * 256 + c]);
}

// ---------------- grid barrier: R13-proven (single gen, release/acquire) ----------------
DI unsigned atom_add_rel(unsigned* p, unsigned v){
    unsigned old;
    asm volatile("atom.add.release.gpu.u32 %0, [%1], %2;" : "=r"(old) : "l"(p), "r"(v) : "memory");
    return old;
}
DI unsigned ld_acq(unsigned* p){
    unsigned v;
    asm volatile("ld.acquire.gpu.u32 %0, [%1];" : "=r"(v) : "l"(p) : "memory");
    return v;
}
DI void st_relaxed(unsigned* p, unsigned v){
    asm volatile("st.relaxed.gpu.u32 [%0], %1;" :: "l"(p), "r"(v) : "memory");
}
DI void gsync(unsigned &gen) {
    __syncthreads();
    if (threadIdx.x == 0) {
        if (atom_add_rel(&g_cnt, 1u) == NBLK - 1u) {
            st_relaxed(&g_cnt, 0u);
            atom_add_rel(&g_gen, 1u);
        }
        while (ld_acq(&g_gen) == gen) { }
    }
    __syncthreads();
    gen++;
}

// ---------------- persistent scan: ppre GEMM + s0 softmax + 255 steps ----------------
__global__ void __launch_bounds__(256, 2)
k_scan(float* __restrict__ o_smp, float* __restrict__ o_hs, float* __restrict__ lg,
       float* __restrict__ ppre, const float* __restrict__ gum,
       const int*   __restrict__ act,
       const float* __restrict__ wi, const float* __restrict__ bi,
       const float* __restrict__ bh, const float* __restrict__ post_b,
       const void*  __restrict__ tau_ptr,
       float* __restrict__ Gpart, float* __restrict__ Lpart)
{
    extern __shared__ char dyn[];
    SmemGemm* sm = (SmemGemm*)dyn;
    unsigned gen = ld_acq(&g_gen);
    const float tau = decode_tau(tau_ptr);
    const int tid  = threadIdx.x;
    const int gtid = blockIdx.x * 256 + tid;
    const int warp = blockIdx.x * 8 + (tid >> 5);
    const int lane = tid & 31;

    // ---- pre-phase P0: ppre = enc @ post_w_bot + post_b (2048 tasks)
    for (int task = blockIdx.x; task < 2048; task += NBLK) {
        int mt = task >> 3, nt = task & 7;
        const bf16* Ah = bENCh + (long)mt * 64 * 1024;
        const bf16* Al = bENCl + (long)mt * 64 * 1024;
        mma_core(Ah, Al, 1024, Ah, Al, 1024, 1LL<<40,
                 bPWbh + nt*128, bPWbl + nt*128, 1024, 1024,
                 ppre + (long)mt * 64 * 1024 + nt*128, 1024,
                 post_b + nt*128, 0, nullptr, nullptr, 0, sm);
        __syncthreads();
    }
    gsync(gen);

    // ---- pre-phase P0b: s0 = gumbel_softmax(ppre[:,0] + gum[0])
    for (int g = warp; g < 2048; g += NBLK * 8) {
        int b = g >> 5, l = g & 31;
        int n = l * 32 + lane;
        float x = (ppre[(long)b * 262144 + n] + gum[((long)b * 32 + l) * 32 + lane]) / tau;
        float m = x;
#pragma unroll
        for (int o = 16; o; o >>= 1) m = fmaxf(m, __shfl_xor_sync(0xffffffffu, m, o));
        float e = expf(x - m);
        float s = e;
#pragma unroll
        for (int o = 16; o; o >>= 1) s += __shfl_xor_sync(0xffffffffu, s, o);
        float pv = e / s;
        long oidx = (long)b * ROWSTRIDE_OUT + n;
        o_smp[oidx] = pv;
        fsplit(pv, bSMPh[oidx], bSMPl[oidx]);
    }
    gsync(gen);

    // ---- main loop ----
    for (int t = 0; t < SM1n; t++) {
        // phase 1: gates partials ; 256 tasks = 8 Ksplit x 32 Ntiles
        if (blockIdx.x < 256) {
            int ks = blockIdx.x >> 5;
            int nt = blockIdx.x & 31;
            const bf16 *Ah, *Al; long long lda;
            if (ks < 4) {
                Ah = bSMPh + (long)t*1024 + ks*256;
                Al = bSMPl + (long)t*1024 + ks*256;
                lda = ROWSTRIDE_OUT;
            } else if (t == 0) {
                Ah = bH0h + (ks-4)*256; Al = bH0l + (ks-4)*256; lda = 1024;
            } else {
                Ah = bHSh + (long)(t-1)*1024 + (ks-4)*256;
                Al = bHSl + (long)(t-1)*1024 + (ks-4)*256;
                lda = ROWSTRIDE_OUT;
            }
            mma_core(Ah, Al, lda, Ah, Al, lda, 1LL<<40,
                     bW4h + (long)(ks*256)*4096 + nt*128,
                     bW4l + (long)(ks*256)*4096 + nt*128, 4096, 256,
                     Gpart + (long)ks*262144 + nt*128, 4096,
                     nullptr, 0, nullptr, nullptr, 0, sm);
        }
        gsync(gen);

        // phase 2: GRU combine -> h_new, float4-vectorized (16384 tasks of 4 elems)
        for (int i4 = gtid; i4 < 16384; i4 += NBLK * 256) {
            int b = i4 >> 8, j = (i4 & 255) << 2;
            int a = act[b * 256 + t];
            const float* on = wi + (long)(1024 + a) * 3072;
            long bb = (long)b * 4096;
            float4 sr  = *(const float4*)(on + j);
            float4 sz  = *(const float4*)(on + 1024 + j);
            float4 inn = *(const float4*)(on + 2048 + j);
            float4 vbi0 = *(const float4*)(bi + j);
            float4 vbi1 = *(const float4*)(bi + 1024 + j);
            float4 vbi2 = *(const float4*)(bi + 2048 + j);
            float4 vbh0 = *(const float4*)(bh + j);
            float4 vbh1 = *(const float4*)(bh + 1024 + j);
            float4 hn   = *(const float4*)(bh + 2048 + j);
            sr.x += vbi0.x + vbh0.x; sr.y += vbi0.y + vbh0.y;
            sr.z += vbi0.z + vbh0.z; sr.w += vbi0.w + vbh0.w;
            sz.x += vbi1.x + vbh1.x; sz.y += vbi1.y + vbh1.y;
            sz.z += vbi1.z + vbh1.z; sz.w += vbi1.w + vbh1.w;
            inn.x += vbi2.x; inn.y += vbi2.y; inn.z += vbi2.z; inn.w += vbi2.w;
#pragma unroll
            for (int ks = 0; ks < 8; ks++) {
                const float* G = Gpart + (long)ks * 262144 + bb;
                float4 g0 = *(const float4*)(G + j);
                float4 g1 = *(const float4*)(G + 1024 + j);
                float4 g2 = *(const float4*)(G + 2048 + j);
                float4 g3 = *(const float4*)(G + 3072 + j);
                sr.x += g0.x; sr.y += g0.y; sr.z += g0.z; sr.w += g0.w;
                sz.x += g1.x; sz.y += g1.y; sz.z += g1.z; sz.w += g1.w;
                inn.x += g2.x; inn.y += g2.y; inn.z += g2.z; inn.w += g2.w;
                hn.x += g3.x; hn.y += g3.y; hn.z += g3.z; hn.w += g3.w;
            }
            long oidx = ((long)b * 255 + t) * 1024 + j;
            float4 hp = (t == 0) ? make_float4(0.f,0.f,0.f,0.f)
                                 : *(const float4*)(o_hs + oidx - 1024);
            float hv[4], hpv[4] = {hp.x, hp.y, hp.z, hp.w};
            float srv[4] = {sr.x, sr.y, sr.z, sr.w};
            float szv[4] = {sz.x, sz.y, sz.z, sz.w};
            float inv[4] = {inn.x, inn.y, inn.z, inn.w};
            float hnv[4] = {hn.x, hn.y, hn.z, hn.w};
            bf16 hh[4], hl[4];
#pragma unroll
            for (int q = 0; q < 4; q++) {
                float r = sigm(srv[q]), z = sigm(szv[q]);
                float nn = tanhf(inv[q] + r * hnv[q]);
                hv[q] = (1.0f - z) * nn + z * hpv[q];
                fsplit(hv[q], hh[q], hl[q]);
            }
            *(float4*)(o_hs + oidx) = make_float4(hv[0], hv[1], hv[2], hv[3]);
            *(uint2*)(bHSh + oidx) = *(const uint2*)hh;
            *(uint2*)(bHSl + oidx) = *(const uint2*)hl;
        }
        gsync(gen);

        // phase 3: logits partials ; 128 tasks = 16 Ksplit x 8 Ntiles (K=64)
        if (blockIdx.x < 128) {
            int ks = blockIdx.x >> 3;
            int nt = blockIdx.x & 7;
            const bf16* Ah = bHSh + (long)t*1024 + ks*64;
            const bf16* Al = bHSl + (long)t*1024 + ks*64;
            mma_core(Ah, Al, ROWSTRIDE_OUT, Ah, Al, ROWSTRIDE_OUT, 1LL<<40,
                     bPWth + (long)(ks*64)*1024 + nt*128,
                     bPWtl + (long)(ks*64)*1024 + nt*128, 1024, 64,
                     Lpart + (long)ks*65536 + nt*128, 1024,
                     nullptr, 0, nullptr, nullptr, 0, sm);
        }
        gsync(gen);

        // phase 4: sum Lpart + ppre, write lg, gumbel softmax -> s_{t+1}
        for (int g = warp; g < 2048; g += NBLK * 8) {
            int b = g >> 5, l = g & 31;
            int n = l * 32 + lane;
            float acc = 0.0f;
#pragma unroll
            for (int ks = 0; ks < 16; ks++) acc += Lpart[(long)ks * 65536 + b * 1024 + n];
            float logit = acc + ppre[((long)b * 256 + t + 1) * 1024 + n];
            lg[((long)b * 255 + t) * 1024 + n] = logit;
            if (t < SM1n - 1) {
                float x = (logit + gum[(long)(t + 1) * 65536 + ((long)b * 32 + l) * 32 + lane]) / tau;
                float m = x;
#pragma unroll
                for (int o = 16; o; o >>= 1) m = fmaxf(m, __shfl_xor_sync(0xffffffffu, m, o));
                float e = expf(x - m);
                float s = e;
#pragma unroll
                for (int o = 16; o; o >>= 1) s += __shfl_xor_sync(0xffffffffu, s, o);
                float pv = e / s;
                long oidx = ((long)b * 255 + (t + 1)) * 1024 + n;
                o_smp[oidx] = pv;
                fsplit(pv, bSMPh[oidx], bSMPl[oidx]);
            }
        }
        gsync(gen);
    }
}

// ---------------- KL ----------------
__global__ void k_kl(const float* __restrict__ post, const float* __restrict__ prior,
                     float* __restrict__ klbt)
{
    int row = blockIdx.x;
    int wid = threadIdx.x >> 5, lane = threadIdx.x & 31;
    float acc = 0.0f;
    for (int l = wid; l < 32; l += 8) {
        long base = (long)row * 1024 + l * 32 + lane;
        float xp = post[base], xq = prior[base];
        float mp = xp, mq = xq;
#pragma unroll
        for (int o = 16; o; o >>= 1) {
            mp = fmaxf(mp, __shfl_xor_sync(0xffffffffu, mp, o));
            mq = fmaxf(mq, __shfl_xor_sync(0xffffffffu, mq, o));
        }
        float ep = expf(xp - mp), eq = expf(xq - mq);
        float sp = ep, sq = eq;
#pragma unroll
        for (int o = 16; o; o >>= 1) {
            sp += __shfl_xor_sync(0xffffffffu, sp, o);
            sq += __shfl_xor_sync(0xffffffffu, sq, o);
        }
        float lpp = xp - mp - logf(sp);
        float lpq = xq - mq - logf(sq);
        float pp = expf(lpp), pq = expf(lpq);
        acc += 0.8f * pp * (lpp - lpq) + 0.2f * pq * (lpq - lpp);
    }
    __shared__ float red[256];
    red[threadIdx.x] = acc; __syncthreads();
    for (int s = 128; s > 0; s >>= 1) { if (threadIdx.x < s) red[threadIdx.x] += red[threadIdx.x + s]; __syncthreads(); }
    if (threadIdx.x == 0) klbt[row] = fmaxf(red[0] - 1.0f, 0.0f);
}

__global__ void k_klreduce(const float* __restrict__ klbt, float* __restrict__ out)
{
    int b = blockIdx.x, t = threadIdx.x;
    __shared__ float red[256];
    red[t] = (t < 255) ? klbt[b * 255 + t] : 0.0f;
    __syncthreads();
    for (int s = 128; s > 0; s >>= 1) { if (t < s) red[t] += red[t + s]; __syncthreads(); }
    if (t == 0) out[b] = red[0] * (1.0f / 255.0f);
}

__global__ void k_reward(const float* __restrict__ hs, const float* __restrict__ smp,
                         const float* __restrict__ rw, const float* __restrict__ rb,
                         float* __restrict__ out)
{
    int row = blockIdx.x * 8 + (threadIdx.x >> 5);
    int lane = threadIdx.x & 31;
    if (row >= 64 * 255) return;
    float acc = 0.0f;
    for (int k = lane; k < 1024; k += 32) acc += hs[(long)row * 1024 + k] * rw[k];
    for (int k = lane; k < 1024; k += 32) acc += smp[(long)row * 1024 + k] * rw[1024 + k];
#pragma unroll
    for (int o = 16; o; o >>= 1) acc += __shfl_xor_sync(0xffffffffu, acc, o);
    if (lane == 0) out[row] = acc + rb[0];
}

// ---------------- host ----------------
extern "C" void kernel_launch(void* const* d_in, const int* in_sizes, int n_in,
                              void* d_out, int out_size)
{
    const float* obs    = (const float*)d_in[0];
    const int*   act    = (const int*)  d_in[1];
    const float* gum    = (const float*)d_in[2];
    const void*  tau    =               d_in[3];
    const float* ln_g   = (const float*)d_in[4];
    const float* ln_b   = (const float*)d_in[5];
    const float* enc_w1 = (const float*)d_in[6];
    const float* enc_b1 = (const float*)d_in[7];
    const float* enc_w2 = (const float*)d_in[8];
    const float* enc_b2 = (const float*)d_in[9];
    const float* gru_wi = (const float*)d_in[10];
    const float* gru_wh = (const float*)d_in[11];
    const float* gru_bi = (const float*)d_in[12];
    const float* gru_bh = (const float*)d_in[13];
    const float* prior_w= (const float*)d_in[14];
    const float* prior_b= (const float*)d_in[15];
    const float* post_w = (const float*)d_in[16];
    const float* post_b = (const float*)d_in[17];
    const float* dec_w1 = (const float*)d_in[18];
    const float* dec_b1 = (const float*)d_in[19];
    const float* dec_w2 = (const float*)d_in[20];
    const float* dec_b2 = (const float*)d_in[21];
    const float* rew_w  = (const float*)d_in[22];
    const float* rew_b  = (const float*)d_in[23];

    float* out     = (float*)d_out;
    float* o_recon = out;
    float* o_rew   = out + REW_OFF;
    float* o_kl    = out + KL_OFF;
    float* o_hs    = out + HS_OFF;
    float* o_smp   = out + SMP_OFF;

    cudaFuncSetAttribute(mma_sgemm, cudaFuncAttributeMaxDynamicSharedMemorySize, SMEMSZ);
    cudaFuncSetAttribute(k_scan,    cudaFuncAttributeMaxDynamicSharedMemorySize, SMEMSZ);

#define SYM(T, var, sym) T* var; cudaGetSymbolAddress((void**)&var, sym)
    SYM(float, ppre, g_ppre);  SYM(float, lg, g_logits);  SYM(float, pri, g_prior);
    SYM(float, klbt, g_klbt);  SYM(float, Gp, g_Gpart);   SYM(float, Lp, g_Lpart);
    SYM(bf16, prh, bPRh);   SYM(bf16, prl, bPRl);
    SYM(bf16, dw1h, bDW1h); SYM(bf16, dw1l, bDW1l);
    SYM(bf16, dw2h, bDW2h); SYM(bf16, dw2l, bDW2l);
    SYM(bf16, ew1h, bEW1h); SYM(bf16, ew1l, bEW1l);
    SYM(bf16, ew2h, bEW2h); SYM(bf16, ew2l, bEW2l);
    SYM(bf16, xh, bXh);     SYM(bf16, xl, bXl);
    SYM(bf16, y1h, bY1h);   SYM(bf16, y1l, bY1l);
    SYM(bf16, ench, bENCh); SYM(bf16, encl, bENCl);
    SYM(bf16, hsh, bHSh);   SYM(bf16, hsl, bHSl);
    SYM(bf16, smph, bSMPh); SYM(bf16, smpl, bSMPl);
    SYM(bf16, dch, bDCh);   SYM(bf16, dcl, bDCl);
    SYM(bf16, h0h, bH0h);   SYM(bf16, h0l, bH0l);
#undef SYM

    k_init<<<256, 256>>>(h0h, h0l);
    k_prep<<<(int)(PREP_TOTAL / 256), 256>>>(gru_wi, gru_wh, enc_w1, enc_w2,
                                             post_w, prior_w, dec_w1, dec_w2);
    k_ln<<<16384, 256>>>(obs, ln_g, ln_b, xh, xl);
    mma_sgemm<<<dim3(8,256), 256, SMEMSZ>>>(xh, xl, 256, xh, xl, 256, 1LL<<40,
        ew1h, ew1l, 1024, 256, enc_b1, 1, nullptr, 0, y1h, y1l, 1024);
    mma_sgemm<<<dim3(8,256), 256, SMEMSZ>>>(y1h, y1l, 1024, y1h, y1l, 1024, 1LL<<40,
        ew2h, ew2l, 1024, 1024, enc_b2, 1, nullptr, 0, ench, encl, 1024);

    // persistent scan
    k_scan<<<NBLK, 256, SMEMSZ>>>(o_smp, o_hs, lg, ppre, gum, act,
                                  gru_wi, gru_bi, gru_bh, post_b, tau, Gp, Lp);

    // epilogue heads
    mma_sgemm<<<dim3(8,255), 256, SMEMSZ>>>(hsh, hsl, 1024, hsh, hsl, 1024, 1LL<<40,
        prh, prl, 1024, 1024, prior_b, 0, pri, 1024, nullptr, nullptr, 0);
    k_kl<<<64 * 255, 256>>>(lg, pri, klbt);
    k_klreduce<<<64, 256>>>(klbt, o_kl);
    mma_sgemm<<<dim3(8,255), 256, SMEMSZ>>>(hsh, hsl, 1024, smph, smpl, 1024, 1024,
        dw1h, dw1l, 1024, 2048, dec_b1, 1, nullptr, 0, dch, dcl, 1024);
    mma_sgemm<<<dim3(2,255), 256, SMEMSZ>>>(dch, dcl, 1024, dch, dcl, 1024, 1LL<<40,
        dw2h, dw2l, 256, 1024, dec_b2, 0, o_recon, 256, nullptr, nullptr, 0);
    k_reward<<<2040, 256>>>(o_hs, o_smp, rew_w, rew_b, o_rew);

    (void)in_sizes; (void)n_in; (void)out_size;
}

// round 16
// speedup vs baseline: 1.2434x; 1.0391x over previous
#include <cuda_runtime.h>
#include <cuda_bf16.h>

// ---------------- problem constants ----------------
#define SM1n  255
#define NBLK  296          // 2 persistent blocks per SM (148 SMs)
#define REW_OFF  4177920L
#define KL_OFF   4194240L
#define HS_OFF   4194304L
#define SMP_OFF  20905984L
#define ROWSTRIDE_OUT 261120L   // 255*1024

typedef unsigned long long ull;
typedef __nv_bfloat16 bf16;
#define DI __device__ __forceinline__

// ---------------- fp32 scratch ----------------
__device__ float g_ppre  [64L*256*1024];
__device__ float g_logits[64L*255*1024];
__device__ float g_prior [64L*255*1024];
__device__ float g_klbt  [64L*255];
__device__ float g_Gpart [8L*64*4096];
__device__ float g_Lpart [16L*64*1024];
__device__ unsigned g_cnt = 0;
__device__ unsigned g_gen = 0;

// ---------------- bf16 limb buffers (hi, lo) ----------------
__device__ bf16 bW4h [2048L*4096], bW4l [2048L*4096];
__device__ bf16 bPWth[1024L*1024], bPWtl[1024L*1024];
__device__ bf16 bPWbh[1024L*1024], bPWbl[1024L*1024];
__device__ bf16 bEW1h[256L*1024],  bEW1l[256L*1024];
__device__ bf16 bEW2h[1024L*1024], bEW2l[1024L*1024];
__device__ bf16 bPRh [1024L*1024], bPRl [1024L*1024];
__device__ bf16 bDW1h[2048L*1024], bDW1l[2048L*1024];
__device__ bf16 bDW2h[1024L*256],  bDW2l[1024L*256];
__device__ bf16 bXh  [64L*256*256],  bXl  [64L*256*256];
__device__ bf16 bY1h [64L*256*1024], bY1l [64L*256*1024];
__device__ bf16 bENCh[64L*256*1024], bENCl[64L*256*1024];
__device__ bf16 bHSh [64L*255*1024], bHSl [64L*255*1024];
__device__ bf16 bSMPh[64L*255*1024], bSMPl[64L*255*1024];
__device__ bf16 bDCh [64L*255*1024], bDCl [64L*255*1024];
__device__ bf16 bH0h [64L*1024],     bH0l [64L*1024];

DI float decode_tau(const void* p) {
    unsigned u = *(const unsigned*)p;
    if (u == 0u) return 0.0f;
    if ((u & 0x7f800000u) == 0u) return (float)(int)u;
    return __uint_as_float(u);
}
DI float sigm(float x) { return 1.0f / (1.0f + expf(-x)); }
DI void fsplit(float v, bf16& h, bf16& l) {
    h = __float2bfloat16(v);
    l = __float2bfloat16(v - __bfloat162float(h));
}

// ---------------- mma helpers ----------------
DI unsigned sptr(const void* p){ return (unsigned)__cvta_generic_to_shared(p); }
DI void ldsm4(unsigned r[4], unsigned a){
    asm volatile("ldmatrix.sync.aligned.m8n8.x4.shared.b16 {%0,%1,%2,%3}, [%4];"
        : "=r"(r[0]),"=r"(r[1]),"=r"(r[2]),"=r"(r[3]) : "r"(a));
}
DI void ldsm4t(unsigned r[4], unsigned a){
    asm volatile("ldmatrix.sync.aligned.m8n8.x4.trans.shared.b16 {%0,%1,%2,%3}, [%4];"
        : "=r"(r[0]),"=r"(r[1]),"=r"(r[2]),"=r"(r[3]) : "r"(a));
}
DI void mmab(float c[4], const unsigned a[4], unsigned b0, unsigned b1){
    asm volatile("mma.sync.aligned.m16n8k16.row.col.f32.bf16.bf16.f32 "
        "{%0,%1,%2,%3},{%4,%5,%6,%7},{%8,%9},{%0,%1,%2,%3};"
        : "+f"(c[0]),"+f"(c[1]),"+f"(c[2]),"+f"(c[3])
        : "r"(a[0]),"r"(a[1]),"r"(a[2]),"r"(a[3]),"r"(b0),"r"(b1));
}
DI void cpa16(unsigned dst, const void* src){
    asm volatile("cp.async.cg.shared.global [%0], [%1], 16;" :: "r"(dst), "l"(src));
}
DI void cpa_commit(){ asm volatile("cp.async.commit_group;" ::: "memory"); }
DI void cpa_wait1(){ asm volatile("cp.async.wait_group 1;" ::: "memory"); }
DI void cpa_wait0(){ asm volatile("cp.async.wait_group 0;" ::: "memory"); }

struct SmemGemm {
    bf16 A[3][2][64*40];    // [stage][limb][m64 x k32 pad40]
    bf16 B[3][2][32*136];   // [stage][limb][k32 x n128 pad136]
};
#define SMEMSZ ((int)sizeof(SmemGemm))

// ============= core 64x128 GEMM via bf16x3 mma, 256 thr, 3-stage cp.async =============
// warp grid: 2 (M) x 4 (N); each warp computes 32 rows x 32 cols.
DI void mma_core(const bf16* __restrict__ A1h, const bf16* __restrict__ A1l, long long lda1,
                 const bf16* __restrict__ A2h, const bf16* __restrict__ A2l, long long lda2, long long K1,
                 const bf16* __restrict__ Wh,  const bf16* __restrict__ Wl,  long long ldw, int K,
                 float* __restrict__ Cf, long long ldc,
                 const float* __restrict__ bias, int relu,
                 bf16* __restrict__ Coh, bf16* __restrict__ Col, long long ldco,
                 SmemGemm* sm)
{
    const int tid  = threadIdx.x;
    const int lane = tid & 31, wid = tid >> 5;
    const int mw = wid >> 2;
    const int nw = wid & 3;
    const int arow = tid >> 2, acol = (tid & 3) << 3;
    const int brow = tid >> 3, bcol = (tid & 7) << 4;
    const int nch = K >> 5;

    float acc[2][4][4];
#pragma unroll
    for (int i = 0; i < 2; i++)
#pragma unroll
        for (int j = 0; j < 4; j++)
#pragma unroll
            for (int q = 0; q < 4; q++) acc[i][j][q] = 0.0f;

    // chunk loader: global -> smem stage via cp.async (6 x 16B per thread)
    auto load_chunk = [&](int c, int st) {
        long long k = (long long)c * 32 + acol;
        const bf16 *ph, *pl; long long off;
        if (k < K1) { ph = A1h; pl = A1l; off = (long long)arow*lda1 + k; }
        else        { ph = A2h; pl = A2l; off = (long long)arow*lda2 + (k - K1); }
        cpa16(sptr(&sm->A[st][0][arow*40 + acol]), ph + off);
        cpa16(sptr(&sm->A[st][1][arow*40 + acol]), pl + off);
        long long wrow = (long long)c * 32 + brow;
        cpa16(sptr(&sm->B[st][0][brow*136 + bcol]),     Wh + wrow*ldw + bcol);
        cpa16(sptr(&sm->B[st][0][brow*136 + bcol + 8]), Wh + wrow*ldw + bcol + 8);
        cpa16(sptr(&sm->B[st][1][brow*136 + bcol]),     Wl + wrow*ldw + bcol);
        cpa16(sptr(&sm->B[st][1][brow*136 + bcol + 8]), Wl + wrow*ldw + bcol + 8);
        cpa_commit();
    };

    load_chunk(0, 0);
    if (nch > 1) load_chunk(1, 1);

    for (int c = 0; c < nch; c++) {
        if (c + 2 < nch) cpa_wait1(); else cpa_wait0();
        __syncthreads();
        if (c + 2 < nch) load_chunk(c + 2, (c + 2) % 3);
        const int p = c % 3;

#pragma unroll
        for (int kk = 0; kk < 2; kk++) {
            unsigned ah[2][4], al[2][4];
#pragma unroll
            for (int mt = 0; mt < 2; mt++) {
                int aoff = (mw*32 + mt*16 + (lane & 15))*40 + kk*16 + ((lane >> 4) << 3);
                ldsm4(ah[mt], sptr(&sm->A[p][0][aoff]));
                ldsm4(al[mt], sptr(&sm->A[p][1][aoff]));
            }
            int brow0 = kk*16 + (lane & 7) + (lane & 8);
#pragma unroll
            for (int g = 0; g < 2; g++) {
                int boff = brow0*136 + nw*32 + g*16 + ((lane & 16) >> 1);
                unsigned bh[4], bl[4];
                ldsm4t(bh, sptr(&sm->B[p][0][boff]));
                ldsm4t(bl, sptr(&sm->B[p][1][boff]));
#pragma unroll
                for (int mt = 0; mt < 2; mt++) {
                    mmab(acc[mt][g*2],   ah[mt], bh[0], bh[1]);
                    mmab(acc[mt][g*2],   ah[mt], bl[0], bl[1]);
                    mmab(acc[mt][g*2],   al[mt], bh[0], bh[1]);
                    mmab(acc[mt][g*2+1], ah[mt], bh[2], bh[3]);
                    mmab(acc[mt][g*2+1], ah[mt], bl[2], bl[3]);
                    mmab(acc[mt][g*2+1], al[mt], bh[2], bh[3]);
                }
            }
        }
    }
    __syncthreads();   // protect smem for next call

#pragma unroll
    for (int mt = 0; mt < 2; mt++) {
        const int r0 = mw*32 + mt*16 + (lane >> 2);
#pragma unroll
        for (int n8 = 0; n8 < 4; n8++) {
            int col = nw*32 + n8*8 + (lane & 3)*2;
            float v00 = acc[mt][n8][0], v01 = acc[mt][n8][1];
            float v10 = acc[mt][n8][2], v11 = acc[mt][n8][3];
            if (bias) {
                float b0 = bias[col], b1 = bias[col+1];
                v00 += b0; v01 += b1; v10 += b0; v11 += b1;
            }
            if (relu) {
                v00 = fmaxf(v00, 0.f); v01 = fmaxf(v01, 0.f);
                v10 = fmaxf(v10, 0.f); v11 = fmaxf(v11, 0.f);
            }
            if (Cf) {
                *(float2*)(Cf + (long long)r0*ldc + col)     = make_float2(v00, v01);
                *(float2*)(Cf + (long long)(r0+8)*ldc + col) = make_float2(v10, v11);
            }
            if (Coh) {
                bf16 h0,l0,h1,l1;
                fsplit(v00,h0,l0); fsplit(v01,h1,l1);
                *(__nv_bfloat162*)(Coh + (long long)r0*ldco + col) = __nv_bfloat162(h0,h1);
                *(__nv_bfloat162*)(Col + (long long)r0*ldco + col) = __nv_bfloat162(l0,l1);
                fsplit(v10,h0,l0); fsplit(v11,h1,l1);
                *(__nv_bfloat162*)(Coh + (long long)(r0+8)*ldco + col) = __nv_bfloat162(h0,h1);
                *(__nv_bfloat162*)(Col + (long long)(r0+8)*ldco + col) = __nv_bfloat162(l0,l1);
            }
        }
    }
}

// ---------------- global GEMM wrapper (2 blocks/SM) ----------------
__global__ void __launch_bounds__(256, 2)
mma_sgemm(const bf16* A1h, const bf16* A1l, long long lda1,
          const bf16* A2h, const bf16* A2l, long long lda2, long long K1,
          const bf16* Wh, const bf16* Wl, long long ldw, int K,
          const float* bias, int relu,
          float* Cf, long long ldc,
          bf16* Coh, bf16* Col, long long ldco)
{
    extern __shared__ char dyn[];
    SmemGemm* sm = (SmemGemm*)dyn;
    long long m0 = (long long)blockIdx.y * 64;
    long long n0 = (long long)blockIdx.x * 128;
    mma_core(A1h + m0*lda1, A1l + m0*lda1, lda1,
             A2h + m0*lda2, A2l + m0*lda2, lda2, K1,
             Wh + n0, Wl + n0, ldw, K,
             Cf ? Cf + m0*ldc + n0 : nullptr, ldc,
             bias ? bias + n0 : nullptr, relu,
             Coh ? Coh + m0*ldco + n0 : nullptr,
             Col ? Col + m0*ldco + n0 : nullptr, ldco, sm);
}

// ---------------- GRU combine for one element ----------------
DI float gru_elem(const float* __restrict__ Gpart, const float* __restrict__ on,
                  const float* __restrict__ bi, const float* __restrict__ bh,
                  const float* __restrict__ o_hs, int b, int j, int t)
{
    long bb = (long)b * 4096;
    float sr  = on[j]        + bi[j]        + bh[j];
    float sz  = on[1024+j]   + bi[1024+j]   + bh[1024+j];
    float inn = on[2048+j]   + bi[2048+j];
    float hn  = bh[2048+j];
#pragma unroll
    for (int ks = 0; ks < 8; ks++) {
        const float* G = Gpart + (long)ks * 262144 + bb;
        sr  += G[j];
        sz  += G[1024 + j];
        inn += G[2048 + j];
        hn  += G[3072 + j];
    }
    float r = sigm(sr), z = sigm(sz);
    float nn = tanhf(inn + r * hn);
    float hp = (t == 0) ? 0.0f : o_hs[((long)b * 255 + t - 1) * 1024 + j];
    return (1.0f - z) * nn + z * hp;
}

// ---------------- k_init: h0 limbs ----------------
__global__ void k_init(bf16* __restrict__ h, bf16* __restrict__ l)
{
    int i = blockIdx.x * 256 + threadIdx.x;
    if (i < 65536) { h[i] = __float2bfloat16(0.f); l[i] = __float2bfloat16(0.f); }
}

// ---------------- k_prep: ALL weight conversions ----------------
#define PREP_TOTAL 15204352L
__global__ void k_prep(const float* __restrict__ wi, const float* __restrict__ wh,
                       const float* __restrict__ enc_w1, const float* __restrict__ enc_w2,
                       const float* __restrict__ post_w, const float* __restrict__ prior_w,
                       const float* __restrict__ dec_w1, const float* __restrict__ dec_w2)
{
    long i = (long)blockIdx.x * 256 + threadIdx.x;
    if (i < 8388608L) {
        int n = (int)(i & 4095);
        int k = (int)(i >> 12);
        float v;
        if (k < 1024) {
            v = (n < 3072) ? wi[(long)k * 3072 + n] : 0.0f;
        } else {
            int k2 = k - 1024;
            if      (n < 2048) v = wh[(long)k2 * 3072 + n];
            else if (n < 3072) v = 0.0f;
            else               v = wh[(long)k2 * 3072 + 2048 + (n - 3072)];
        }
        fsplit(v, bW4h[i], bW4l[i]);
        return;
    }
    long j = i - 8388608L;
    if (j < 262144L)  { fsplit(enc_w1[j], bEW1h[j], bEW1l[j]); return; }
    j -= 262144L;
    if (j < 1048576L) { fsplit(enc_w2[j], bEW2h[j], bEW2l[j]); return; }
    j -= 1048576L;
    if (j < 1048576L) { fsplit(post_w[j], bPWth[j], bPWtl[j]); return; }
    j -= 1048576L;
    if (j < 1048576L) { fsplit(post_w[1048576L + j], bPWbh[j], bPWbl[j]); return; }
    j -= 1048576L;
    if (j < 1048576L) { fsplit(prior_w[j], bPRh[j], bPRl[j]); return; }
    j -= 1048576L;
    if (j < 2097152L) { fsplit(dec_w1[j], bDW1h[j], bDW1l[j]); return; }
    j -= 2097152L;
    fsplit(dec_w2[j], bDW2h[j], bDW2l[j]);
}

// ---------------- LayerNorm -> bf16 limbs ----------------
__global__ void k_ln(const float* __restrict__ obs, const float* __restrict__ g,
                     const float* __restrict__ bvec, bf16* __restrict__ oh, bf16* __restrict__ ol)
{
    int row = blockIdx.x, c = threadIdx.x;
    __shared__ float red[256];
    float x = obs[(long)row * 256 + c];
    red[c] = x; __syncthreads();
    for (int s = 128; s > 0; s >>= 1) { if (c < s) red[c] += red[c + s]; __syncthreads(); }
    float mu = red[0] * (1.0f / 256.0f);
    __syncthreads();
    float d = x - mu;
    red[c] = d * d; __syncthreads();
    for (int s = 128; s > 0; s >>= 1) { if (c < s) red[c] += red[c + s]; __syncthreads(); }
    float var = red[0] * (1.0f / 256.0f);
    float v = d * rsqrtf(var + 1e-5f) * g[c] + bvec[c];
    fsplit(v, oh[(long)row * 256 + c], ol[(long)row * 256 + c]);
}

// ---------------- grid barrier: R13-proven (single gen, release/acquire) ----------------
DI unsigned atom_add_rel(unsigned* p, unsigned v){
    unsigned old;
    asm volatile("atom.add.release.gpu.u32 %0, [%1], %2;" : "=r"(old) : "l"(p), "r"(v) : "memory");
    return old;
}
DI unsigned ld_acq(unsigned* p){
    unsigned v;
    asm volatile("ld.acquire.gpu.u32 %0, [%1];" : "=r"(v) : "l"(p) : "memory");
    return v;
}
DI void st_relaxed(unsigned* p, unsigned v){
    asm volatile("st.relaxed.gpu.u32 [%0], %1;" :: "l"(p), "r"(v) : "memory");
}
DI void gsync(unsigned &gen) {
    __syncthreads();
    if (threadIdx.x == 0) {
        if (atom_add_rel(&g_cnt, 1u) == NBLK - 1u) {
            st_relaxed(&g_cnt, 0u);
            atom_add_rel(&g_gen, 1u);
        }
        while (ld_acq(&g_gen) == gen) { }
    }
    __syncthreads();
    gen++;
}

// ---------------- persistent scan: ppre GEMM + s0 softmax + 255 steps ----------------
__global__ void __launch_bounds__(256, 2)
k_scan(float* __restrict__ o_smp, float* __restrict__ o_hs, float* __restrict__ lg,
       float* __restrict__ ppre, const float* __restrict__ gum,
       const int*   __restrict__ act,
       const float* __restrict__ wi, const float* __restrict__ bi,
       const float* __restrict__ bh, const float* __restrict__ post_b,
       const void*  __restrict__ tau_ptr,
       float* __restrict__ Gpart, float* __restrict__ Lpart)
{
    extern __shared__ char dyn[];
    SmemGemm* sm = (SmemGemm*)dyn;
    unsigned gen = ld_acq(&g_gen);
    const float tau = decode_tau(tau_ptr);
    const int tid  = threadIdx.x;
    const int gtid = blockIdx.x * 256 + tid;
    const int warp = blockIdx.x * 8 + (tid >> 5);
    const int lane = tid & 31;

    // ---- pre-phase P0: ppre = enc @ post_w_bot + post_b (2048 tasks)
    for (int task = blockIdx.x; task < 2048; task += NBLK) {
        int mt = task >> 3, nt = task & 7;
        const bf16* Ah = bENCh + (long)mt * 64 * 1024;
        const bf16* Al = bENCl + (long)mt * 64 * 1024;
        mma_core(Ah, Al, 1024, Ah, Al, 1024, 1LL<<40,
                 bPWbh + nt*128, bPWbl + nt*128, 1024, 1024,
                 ppre + (long)mt * 64 * 1024 + nt*128, 1024,
                 post_b + nt*128, 0, nullptr, nullptr, 0, sm);
    }
    gsync(gen);

    // ---- pre-phase P0b: s0 = gumbel_softmax(ppre[:,0] + gum[0])
    for (int g = warp; g < 2048; g += NBLK * 8) {
        int b = g >> 5, l = g & 31;
        int n = l * 32 + lane;
        float x = (ppre[(long)b * 262144 + n] + gum[((long)b * 32 + l) * 32 + lane]) / tau;
        float m = x;
#pragma unroll
        for (int o = 16; o; o >>= 1) m = fmaxf(m, __shfl_xor_sync(0xffffffffu, m, o));
        float e = expf(x - m);
        float s = e;
#pragma unroll
        for (int o = 16; o; o >>= 1) s += __shfl_xor_sync(0xffffffffu, s, o);
        float pv = e / s;
        long oidx = (long)b * ROWSTRIDE_OUT + n;
        o_smp[oidx] = pv;
        fsplit(pv, bSMPh[oidx], bSMPl[oidx]);
    }
    gsync(gen);

    // ---- main loop ----
    for (int t = 0; t < SM1n; t++) {
        // phase 1: gates partials ; 256 tasks = 8 Ksplit x 32 Ntiles
        if (blockIdx.x < 256) {
            int ks = blockIdx.x >> 5;
            int nt = blockIdx.x & 31;
            const bf16 *Ah, *Al; long long lda;
            if (ks < 4) {
                Ah = bSMPh + (long)t*1024 + ks*256;
                Al = bSMPl + (long)t*1024 + ks*256;
                lda = ROWSTRIDE_OUT;
            } else if (t == 0) {
                Ah = bH0h + (ks-4)*256; Al = bH0l + (ks-4)*256; lda = 1024;
            } else {
                Ah = bHSh + (long)(t-1)*1024 + (ks-4)*256;
                Al = bHSl + (long)(t-1)*1024 + (ks-4)*256;
                lda = ROWSTRIDE_OUT;
            }
            mma_core(Ah, Al, lda, Ah, Al, lda, 1LL<<40,
                     bW4h + (long)(ks*256)*4096 + nt*128,
                     bW4l + (long)(ks*256)*4096 + nt*128, 4096, 256,
                     Gpart + (long)ks*262144 + nt*128, 4096,
                     nullptr, 0, nullptr, nullptr, 0, sm);
        }
        gsync(gen);

        // phase 2: GRU combine -> h_new (R13 scalar form)
        for (int idx = gtid; idx < 65536; idx += NBLK * 256) {
            int b = idx >> 10, j = idx & 1023;
            int a = act[b * 256 + t];
            const float* on = wi + (long)(1024 + a) * 3072;
            float hnew = gru_elem(Gpart, on, bi, bh, o_hs, b, j, t);
            long oidx = ((long)b * 255 + t) * 1024 + j;
            o_hs[oidx] = hnew;
            fsplit(hnew, bHSh[oidx], bHSl[oidx]);
        }
        gsync(gen);

        // phase 3: logits partials ; 128 tasks = 16 Ksplit x 8 Ntiles (K=64)
        if (blockIdx.x < 128) {
            int ks = blockIdx.x >> 3;
            int nt = blockIdx.x & 7;
            const bf16* Ah = bHSh + (long)t*1024 + ks*64;
            const bf16* Al = bHSl + (long)t*1024 + ks*64;
            mma_core(Ah, Al, ROWSTRIDE_OUT, Ah, Al, ROWSTRIDE_OUT, 1LL<<40,
                     bPWth + (long)(ks*64)*1024 + nt*128,
                     bPWtl + (long)(ks*64)*1024 + nt*128, 1024, 64,
                     Lpart + (long)ks*65536 + nt*128, 1024,
                     nullptr, 0, nullptr, nullptr, 0, sm);
        }
        gsync(gen);

        // phase 4: sum Lpart + ppre, write lg, gumbel softmax -> s_{t+1}
        for (int g = warp; g < 2048; g += NBLK * 8) {
            int b = g >> 5, l = g & 31;
            int n = l * 32 + lane;
            float acc = 0.0f;
#pragma unroll
            for (int ks = 0; ks < 16; ks++) acc += Lpart[(long)ks * 65536 + b * 1024 + n];
            float logit = acc + ppre[((long)b * 256 + t + 1) * 1024 + n];
            lg[((long)b * 255 + t) * 1024 + n] = logit;
            if (t < SM1n - 1) {
                float x = (logit + gum[(long)(t + 1) * 65536 + ((long)b * 32 + l) * 32 + lane]) / tau;
                float m = x;
#pragma unroll
                for (int o = 16; o; o >>= 1) m = fmaxf(m, __shfl_xor_sync(0xffffffffu, m, o));
                float e = expf(x - m);
                float s = e;
#pragma unroll
                for (int o = 16; o; o >>= 1) s += __shfl_xor_sync(0xffffffffu, s, o);
                float pv = e / s;
                long oidx = ((long)b * 255 + (t + 1)) * 1024 + n;
                o_smp[oidx] = pv;
                fsplit(pv, bSMPh[oidx], bSMPl[oidx]);
            }
        }
        gsync(gen);
    }
}

// ---------------- KL ----------------
__global__ void k_kl(const float* __restrict__ post, const float* __restrict__ prior,
                     float* __restrict__ klbt)
{
    int row = blockIdx.x;
    int wid = threadIdx.x >> 5, lane = threadIdx.x & 31;
    float acc = 0.0f;
    for (int l = wid; l < 32; l += 8) {
        long base = (long)row * 1024 + l * 32 + lane;
        float xp = post[base], xq = prior[base];
        float mp = xp, mq = xq;
#pragma unroll
        for (int o = 16; o; o >>= 1) {
            mp = fmaxf(mp, __shfl_xor_sync(0xffffffffu, mp, o));
            mq = fmaxf(mq, __shfl_xor_sync(0xffffffffu, mq, o));
        }
        float ep = expf(xp - mp), eq = expf(xq - mq);
        float sp = ep, sq = eq;
#pragma unroll
        for (int o = 16; o; o >>= 1) {
            sp += __shfl_xor_sync(0xffffffffu, sp, o);
            sq += __shfl_xor_sync(0xffffffffu, sq, o);
        }
        float lpp = xp - mp - logf(sp);
        float lpq = xq - mq - logf(sq);
        float pp = expf(lpp), pq = expf(lpq);
        acc += 0.8f * pp * (lpp - lpq) + 0.2f * pq * (lpq - lpp);
    }
    __shared__ float red[256];
    red[threadIdx.x] = acc; __syncthreads();
    for (int s = 128; s > 0; s >>= 1) { if (threadIdx.x < s) red[threadIdx.x] += red[threadIdx.x + s]; __syncthreads(); }
    if (threadIdx.x == 0) klbt[row] = fmaxf(red[0] - 1.0f, 0.0f);
}

__global__ void k_klreduce(const float* __restrict__ klbt, float* __restrict__ out)
{
    int b = blockIdx.x, t = threadIdx.x;
    __shared__ float red[256];
    red[t] = (t < 255) ? klbt[b * 255 + t] : 0.0f;
    __syncthreads();
    for (int s = 128; s > 0; s >>= 1) { if (t < s) red[t] += red[t + s]; __syncthreads(); }
    if (t == 0) out[b] = red[0] * (1.0f / 255.0f);
}

__global__ void k_reward(const float* __restrict__ hs, const float* __restrict__ smp,
                         const float* __restrict__ rw, const float* __restrict__ rb,
                         float* __restrict__ out)
{
    int row = blockIdx.x * 8 + (threadIdx.x >> 5);
    int lane = threadIdx.x & 31;
    if (row >= 64 * 255) return;
    float acc = 0.0f;
    for (int k = lane; k < 1024; k += 32) acc += hs[(long)row * 1024 + k] * rw[k];
    for (int k = lane; k < 1024; k += 32) acc += smp[(long)row * 1024 + k] * rw[1024 + k];
#pragma unroll
    for (int o = 16; o; o >>= 1) acc += __shfl_xor_sync(0xffffffffu, acc, o);
    if (lane == 0) out[row] = acc + rb[0];
}

// ---------------- host ----------------
extern "C" void kernel_launch(void* const* d_in, const int* in_sizes, int n_in,
                              void* d_out, int out_size)
{
    const float* obs    = (const float*)d_in[0];
    const int*   act    = (const int*)  d_in[1];
    const float* gum    = (const float*)d_in[2];
    const void*  tau    =               d_in[3];
    const float* ln_g   = (const float*)d_in[4];
    const float* ln_b   = (const float*)d_in[5];
    const float* enc_w1 = (const float*)d_in[6];
    const float* enc_b1 = (const float*)d_in[7];
    const float* enc_w2 = (const float*)d_in[8];
    const float* enc_b2 = (const float*)d_in[9];
    const float* gru_wi = (const float*)d_in[10];
    const float* gru_wh = (const float*)d_in[11];
    const float* gru_bi = (const float*)d_in[12];
    const float* gru_bh = (const float*)d_in[13];
    const float* prior_w= (const float*)d_in[14];
    const float* prior_b= (const float*)d_in[15];
    const float* post_w = (const float*)d_in[16];
    const float* post_b = (const float*)d_in[17];
    const float* dec_w1 = (const float*)d_in[18];
    const float* dec_b1 = (const float*)d_in[19];
    const float* dec_w2 = (const float*)d_in[20];
    const float* dec_b2 = (const float*)d_in[21];
    const float* rew_w  = (const float*)d_in[22];
    const float* rew_b  = (const float*)d_in[23];

    float* out     = (float*)d_out;
    float* o_recon = out;
    float* o_rew   = out + REW_OFF;
    float* o_kl    = out + KL_OFF;
    float* o_hs    = out + HS_OFF;
    float* o_smp   = out + SMP_OFF;

    cudaFuncSetAttribute(mma_sgemm, cudaFuncAttributeMaxDynamicSharedMemorySize, SMEMSZ);
    cudaFuncSetAttribute(k_scan,    cudaFuncAttributeMaxDynamicSharedMemorySize, SMEMSZ);

#define SYM(T, var, sym) T* var; cudaGetSymbolAddress((void**)&var, sym)
    SYM(float, ppre, g_ppre);  SYM(float, lg, g_logits);  SYM(float, pri, g_prior);
    SYM(float, klbt, g_klbt);  SYM(float, Gp, g_Gpart);   SYM(float, Lp, g_Lpart);
    SYM(bf16, prh, bPRh);   SYM(bf16, prl, bPRl);
    SYM(bf16, dw1h, bDW1h); SYM(bf16, dw1l, bDW1l);
    SYM(bf16, dw2h, bDW2h); SYM(bf16, dw2l, bDW2l);
    SYM(bf16, ew1h, bEW1h); SYM(bf16, ew1l, bEW1l);
    SYM(bf16, ew2h, bEW2h); SYM(bf16, ew2l, bEW2l);
    SYM(bf16, xh, bXh);     SYM(bf16, xl, bXl);
    SYM(bf16, y1h, bY1h);   SYM(bf16, y1l, bY1l);
    SYM(bf16, ench, bENCh); SYM(bf16, encl, bENCl);
    SYM(bf16, hsh, bHSh);   SYM(bf16, hsl, bHSl);
    SYM(bf16, smph, bSMPh); SYM(bf16, smpl, bSMPl);
    SYM(bf16, dch, bDCh);   SYM(bf16, dcl, bDCl);
    SYM(bf16, h0h, bH0h);   SYM(bf16, h0l, bH0l);
#undef SYM

    k_init<<<256, 256>>>(h0h, h0l);
    k_prep<<<(int)(PREP_TOTAL / 256), 256>>>(gru_wi, gru_wh, enc_w1, enc_w2,
                                             post_w, prior_w, dec_w1, dec_w2);
    k_ln<<<16384, 256>>>(obs, ln_g, ln_b, xh, xl);
    mma_sgemm<<<dim3(8,256), 256, SMEMSZ>>>(xh, xl, 256, xh, xl, 256, 1LL<<40,
        ew1h, ew1l, 1024, 256, enc_b1, 1, nullptr, 0, y1h, y1l, 1024);
    mma_sgemm<<<dim3(8,256), 256, SMEMSZ>>>(y1h, y1l, 1024, y1h, y1l, 1024, 1LL<<40,
        ew2h, ew2l, 1024, 1024, enc_b2, 1, nullptr, 0, ench, encl, 1024);

    // persistent scan
    k_scan<<<NBLK, 256, SMEMSZ>>>(o_smp, o_hs, lg, ppre, gum, act,
                                  gru_wi, gru_bi, gru_bh, post_b, tau, Gp, Lp);

    // epilogue heads
    mma_sgemm<<<dim3(8,255), 256, SMEMSZ>>>(hsh, hsl, 1024, hsh, hsl, 1024, 1LL<<40,
        prh, prl, 1024, 1024, prior_b, 0, pri, 1024, nullptr, nullptr, 0);
    k_kl<<<64 * 255, 256>>>(lg, pri, klbt);
    k_klreduce<<<64, 256>>>(klbt, o_kl);
    mma_sgemm<<<dim3(8,255), 256, SMEMSZ>>>(hsh, hsl, 1024, smph, smpl, 1024, 1024,
        dw1h, dw1l, 1024, 2048, dec_b1, 1, nullptr, 0, dch, dcl, 1024);
    mma_sgemm<<<dim3(2,255), 256, SMEMSZ>>>(dch, dcl, 1024, dch, dcl, 1024, 1LL<<40,
        dw2h, dw2l, 256, 1024, dec_b2, 0, o_recon, 256, nullptr, nullptr, 0);
    k_reward<<<2040, 256>>>(o_hs, o_smp, rew_w, rew_b, o_rew);

    (void)in_sizes; (void)n_in; (void)out_size;
}